// round 15
// baseline (speedup 1.0000x reference)
#include <cuda_runtime.h>

#define NN 384
#define DD 128
#define MARGIN_F 0.2f
#define APB 4
#define NBLK (NN / APB)     // 96 blocks -> single wave
#define NTHR 384            // 12 warps
#define NWARP 12
#define TROW 33             // padded float4 row stride
#define MAXPOS 64
#define NCLS 32
#define TSMEM (NN * TROW * 16)  // 202752 B

typedef unsigned long long u64;

__device__ __forceinline__ u64 ffma2(u64 a, u64 b, u64 c) {
    u64 d;
    asm("fma.rn.f32x2 %0, %1, %2, %3;" : "=l"(d) : "l"(a), "l"(b), "l"(c));
    return d;
}
__device__ __forceinline__ float unpack_sum(u64 p) {
    float lo, hi;
    asm("mov.b64 {%0, %1}, %2;" : "=f"(lo), "=f"(hi) : "l"(p));
    return lo + hi;
}

// Scratch (no allocations allowed)
__device__ float g_total;
__device__ unsigned int g_ctr;

__global__ void __launch_bounds__(NTHR) fused_k(
    const float* __restrict__ feat,
    const int*   __restrict__ y,
    float*       __restrict__ out)
{
    extern __shared__ float4 T4[];       // [row][c] padded, 384 x 33
    const int t = threadIdx.x;           // == column j
    const int ab = blockIdx.x * APB;
    const int w = t >> 5, lane = t & 31;
    const unsigned FULL = 0xFFFFFFFFu;

    __shared__ float4 fa4s[APB][DD / 4];
    __shared__ float  ras[APB];
    __shared__ int    yas[APB];
    __shared__ int    hist[NCLS];
    __shared__ int    cnt[APB];
    __shared__ float  pos_d[APB][MAXPOS];
    __shared__ float  red_f[NWARP];

    // ---- issue all global loads up front ----
    const float4* feat4 = reinterpret_cast<const float4*>(feat);
    float4 pre[16];
#pragma unroll
    for (int i = 0; i < 16; i++)
        pre[i] = feat4[i * NTHR + t];

    float4 av;
    if (t < 128) av = feat4[(ab + w) * (DD / 4) + lane];
    const int yj = __ldg(&y[t]);
    if (t < APB) yas[t] = y[ab + t];

    // init shared counters
    if (t < NCLS) hist[t] = 0;
    if (t < APB) cnt[t] = 0;
    __syncthreads();                      // bar0: inits visible

    atomicAdd(&hist[yj], 1);

    // stage first half of tile, prefetch second half, stage it
#pragma unroll
    for (int i = 0; i < 16; i++) {
        const int f = i * NTHR + t;
        T4[(f >> 5) * TROW + (f & 31)] = pre[i];
    }
#pragma unroll
    for (int i = 16; i < 32; i++)
        pre[i - 16] = feat4[i * NTHR + t];
#pragma unroll
    for (int i = 16; i < 32; i++) {
        const int f = i * NTHR + t;
        T4[(f >> 5) * TROW + (f & 31)] = pre[i - 16];
    }

    // anchors to smem + norms from registers (warps 0..3)
    if (t < 128) {
        fa4s[w][lane] = av;
        float ss = av.x * av.x + av.y * av.y + av.z * av.z + av.w * av.w;
#pragma unroll
        for (int o = 16; o > 0; o >>= 1)
            ss += __shfl_xor_sync(FULL, ss, o);
        if (lane == 0) ras[w] = ss;
    }
    __syncthreads();                      // bar1: tile + anchors + hist done

    // ---- dot phase: full k, packed f32x2 ----
    u64 p0 = 0ull, p1 = 0ull, p2 = 0ull, p3 = 0ull, pr = 0ull;
    {
        const ulonglong2* vr = reinterpret_cast<const ulonglong2*>(&T4[t * TROW]);
        const ulonglong2* A0 = reinterpret_cast<const ulonglong2*>(&fa4s[0][0]);
        const ulonglong2* A1 = reinterpret_cast<const ulonglong2*>(&fa4s[1][0]);
        const ulonglong2* A2 = reinterpret_cast<const ulonglong2*>(&fa4s[2][0]);
        const ulonglong2* A3 = reinterpret_cast<const ulonglong2*>(&fa4s[3][0]);
#pragma unroll
        for (int c = 0; c < DD / 4; c++) {
            const ulonglong2 v = vr[c];
            ulonglong2 a;
            a = A0[c]; p0 = ffma2(a.x, v.x, p0); p0 = ffma2(a.y, v.y, p0);
            a = A1[c]; p1 = ffma2(a.x, v.x, p1); p1 = ffma2(a.y, v.y, p1);
            a = A2[c]; p2 = ffma2(a.x, v.x, p2); p2 = ffma2(a.y, v.y, p2);
            a = A3[c]; p3 = ffma2(a.x, v.x, p3); p3 = ffma2(a.y, v.y, p3);
            pr = ffma2(v.x, v.x, pr); pr = ffma2(v.y, v.y, pr);
        }
    }
    const float rr = unpack_sum(pr);
    const float dts[APB] = {unpack_sum(p0), unpack_sum(p1),
                            unpack_sum(p2), unpack_sum(p3)};

    // ---- d2 + atomic compaction (single barrier) ----
    float d2[APB];
#pragma unroll
    for (int m = 0; m < APB; m++) {
        d2[m] = fmaxf(ras[m] + rr - 2.0f * dts[m], 0.0f);
        if (yj == yas[m] && t != ab + m) {
            const int idx = atomicAdd(&cnt[m], 1);
            pos_d[m][idx] = d2[m] + MARGIN_F;
        }
    }
    __syncthreads();                      // bar2: pos lists + hist complete

    // ---- triplet sums: thread t is candidate negative ----
    float acc = 0.0f;
#pragma unroll
    for (int m = 0; m < APB; m++) {
        const int npm = cnt[m];
        if (yj != yas[m]) {
            const float dn = d2[m];
            for (int i = 0; i < npm; i++) {
                const float v = pos_d[m][i] - dn;
                acc += (v > 0.0f) ? v : 0.0f;
            }
        }
    }

    // ---- reduce + tail ----
#pragma unroll
    for (int off = 16; off > 0; off >>= 1)
        acc += __shfl_down_sync(FULL, acc, off);
    if (lane == 0) red_f[w] = acc;
    __syncthreads();                      // bar3
    if (w == 0) {
        float af = (lane < NWARP) ? red_f[lane] : 0.0f;
        // global count from label histogram (identical in every block)
        const int hcnt = hist[lane];
        float ct = (float)(hcnt * (hcnt - 1) * (NN - hcnt));
#pragma unroll
        for (int off = 16; off > 0; off >>= 1) {
            af += __shfl_down_sync(FULL, af, off);
            ct += __shfl_down_sync(FULL, ct, off);
        }
        if (lane == 0) {
            atomicAdd(&g_total, af);
            __threadfence();
            const unsigned done = atomicAdd(&g_ctr, 1u);
            if (done == NBLK - 1) {
                const float tot = atomicAdd(&g_total, 0.0f);
                out[0] = tot / ct;
                g_total = 0.0f;
                g_ctr   = 0u;
            }
        }
    }
}

extern "C" void kernel_launch(void* const* d_in, const int* in_sizes, int n_in,
                              void* d_out, int out_size) {
    const float* feat = (const float*)d_in[0];
    // d_in[1] = logits (unused by the loss)
    const int*   yv   = (const int*)d_in[2];
    float* out = (float*)d_out;

    static int attr_set = 0;
    if (!attr_set) {
        cudaFuncSetAttribute(fused_k, cudaFuncAttributeMaxDynamicSharedMemorySize,
                             TSMEM);
        attr_set = 1;
    }
    fused_k<<<NBLK, NTHR, TSMEM>>>(feat, yv, out);
}